// round 1
// baseline (speedup 1.0000x reference)
#include <cuda_runtime.h>
#include <cuda_bf16.h>
#include <math.h>
#include <stdint.h>

// Problem constants
#define D_ 512
#define V_ 8192
#define R_ 32768   // B*T*U = 2*256*64

// -------- scratch (static device allocations only) --------
__device__ float g_enc[512 * 512];                 // (B*T, D)
__device__ float g_dec[128 * 512];                 // (B*U, D)
__device__ __nv_bfloat16 g_wvt[8192 * 512];        // Wv transposed [v][d], bf16
__device__ float g_lse[32768];                     // per-row logsumexp

// ---------------------------------------------------------------
// K1: enc = v@W1+b1 (512 rows), dec = t@W2+b2 (128 rows)
// one CTA per row, 256 threads, 2 output cols per thread
// ---------------------------------------------------------------
__global__ void k_encdec(const float* __restrict__ v, const float* __restrict__ t,
                         const float* __restrict__ W1, const float* __restrict__ b1,
                         const float* __restrict__ W2, const float* __restrict__ b2) {
    __shared__ float xrow[512];
    int bid = blockIdx.x, tid = threadIdx.x;
    const float *in, *W, *bias;
    float* out;
    if (bid < 512) { in = v + (size_t)bid * D_; W = W1; bias = b1; out = g_enc + (size_t)bid * D_; }
    else { int r = bid - 512; in = t + (size_t)r * D_; W = W2; bias = b2; out = g_dec + (size_t)r * D_; }
    xrow[tid] = in[tid];
    xrow[tid + 256] = in[tid + 256];
    __syncthreads();
    int e = tid * 2;
    float a0 = bias[e], a1 = bias[e + 1];
    #pragma unroll 4
    for (int d = 0; d < D_; ++d) {
        float x = xrow[d];
        float2 w = *(const float2*)&W[d * D_ + e];
        a0 = fmaf(x, w.x, a0);
        a1 = fmaf(x, w.y, a1);
    }
    out[e] = a0;
    out[e + 1] = a1;
}

// ---------------------------------------------------------------
// K1b: convert Wv (fp32 [d][v]) -> g_wvt (bf16 [v][d])
// ---------------------------------------------------------------
__global__ void k_cvt(const float* __restrict__ Wv) {
    int idx = blockIdx.x * 256 + threadIdx.x;   // 0 .. 1048575 (f4 groups)
    int d = idx >> 11;                          // 2048 float4 per d-row
    int v4 = idx & 2047;
    float4 w = ((const float4*)Wv)[(size_t)d * 2048 + v4];
    int vb = v4 * 4;
    g_wvt[(size_t)(vb + 0) * 512 + d] = __float2bfloat16(w.x);
    g_wvt[(size_t)(vb + 1) * 512 + d] = __float2bfloat16(w.y);
    g_wvt[(size_t)(vb + 2) * 512 + d] = __float2bfloat16(w.z);
    g_wvt[(size_t)(vb + 3) * 512 + d] = __float2bfloat16(w.w);
}

// ---------------------------------------------------------------
// K2: main GEMM + online logsumexp.
// CTA: 128 rows x full V (loops 64 chunks of N=128). 256 threads (8 warps,
// warp grid 4(M) x 2(N)). mma.sync.m16n8k16 bf16 -> fp32.
// sA: h tile [128][520] bf16 (pad -> bank step 4/row, conflict-free frags)
// sB: Wv^T chunk [128 n][136 k] bf16 (pad -> conflict-free frags)
// ---------------------------------------------------------------
__device__ __forceinline__ void mma16816(float* c, const uint32_t* a, const uint32_t* b) {
    asm("mma.sync.aligned.m16n8k16.row.col.f32.bf16.bf16.f32 "
        "{%0,%1,%2,%3}, {%4,%5,%6,%7}, {%8,%9}, {%0,%1,%2,%3};\n"
        : "+f"(c[0]), "+f"(c[1]), "+f"(c[2]), "+f"(c[3])
        : "r"(a[0]), "r"(a[1]), "r"(a[2]), "r"(a[3]), "r"(b[0]), "r"(b[1]));
}

#define SA_STRIDE 520        // bf16 units per A row (260 u32)
#define SB_STRIDE 136        // bf16 units per B row (68 u32)
#define SMEM_A_BYTES (128 * SA_STRIDE * 2)           // 133120
#define SMEM_B_BYTES (128 * SB_STRIDE * 2)           // 34816
#define SMEM_DYN (SMEM_A_BYTES + SMEM_B_BYTES)       // 167936

__global__ void __launch_bounds__(256, 1)
k_gemm(const float* __restrict__ bv, float* __restrict__ out) {
    extern __shared__ char smem[];
    __nv_bfloat16* sA = (__nv_bfloat16*)smem;
    uint32_t* sAu = (uint32_t*)smem;
    uint32_t* sBu = (uint32_t*)(smem + SMEM_A_BYTES);

    __shared__ float pmax[2][128], psum[2][128];
    __shared__ float rmax[128], rsum[128];

    int tid = threadIdx.x;
    int lane = tid & 31, warp = tid >> 5;
    int wm = warp & 3, wn = warp >> 2;     // warp grid 4 x 2
    int q = lane >> 2, l4 = lane & 3;
    int r0 = blockIdx.x * 128;

    // ---- build A tile: h = relu(enc[bt] + dec[bu]) -> bf16 ----
    for (int j = 0; j < 256; ++j) {
        int idx = j * 256 + tid;
        int rl = idx >> 9, d = idx & 511;
        int r = r0 + rl;
        int er = r >> 6;                          // b*T + t
        int dr = ((r >> 14) << 6) | (r & 63);     // b*U + u
        float hv = g_enc[(size_t)er * 512 + d] + g_dec[(size_t)dr * 512 + d];
        hv = hv > 0.f ? hv : 0.f;
        sA[rl * SA_STRIDE + d] = __float2bfloat16(hv);
    }
    if (tid < 128) { rmax[tid] = -1e30f; rsum[tid] = 0.f; }

    const uint32_t* wvu = (const uint32_t*)g_wvt;   // 256 u32 per v-row

    for (int vc = 0; vc < 64; ++vc) {
        int v0 = vc * 128;
        float acc[2][8][4];
        #pragma unroll
        for (int am = 0; am < 2; ++am)
            #pragma unroll
            for (int an = 0; an < 8; ++an)
                #pragma unroll
                for (int jj = 0; jj < 4; ++jj) acc[am][an][jj] = 0.f;

        for (int kb = 0; kb < 4; ++kb) {
            __syncthreads();   // sB (and on first iter: sA fill / pmax) safe to overwrite
            // stage sB: 128 n-rows x 64 u32 of k
            #pragma unroll
            for (int i = 0; i < 32; ++i) {
                int qq = i * 256 + tid;
                int n = qq >> 6, kk = qq & 63;
                sBu[n * 68 + kk] = wvu[(size_t)(v0 + n) * 256 + kb * 64 + kk];
            }
            __syncthreads();

            #pragma unroll
            for (int ks = 0; ks < 8; ++ks) {
                int kc = kb * 64 + ks * 8 + l4;    // u32 column in sA
                uint32_t afr[2][4];
                #pragma unroll
                for (int am = 0; am < 2; ++am) {
                    int rowb = wm * 32 + am * 16 + q;
                    const uint32_t* pa = &sAu[rowb * 260 + kc];
                    afr[am][0] = pa[0];
                    afr[am][1] = pa[8 * 260];
                    afr[am][2] = pa[4];
                    afr[am][3] = pa[8 * 260 + 4];
                }
                uint32_t bfr[8][2];
                #pragma unroll
                for (int an = 0; an < 8; ++an) {
                    const uint32_t* pb = &sBu[(wn * 64 + an * 8 + q) * 68 + ks * 8 + l4];
                    bfr[an][0] = pb[0];
                    bfr[an][1] = pb[4];
                }
                #pragma unroll
                for (int am = 0; am < 2; ++am)
                    #pragma unroll
                    for (int an = 0; an < 8; ++an)
                        mma16816(acc[am][an], afr[am], bfr[an]);
            }
        }

        // ---- epilogue: add bias, store logits, online (max, sumexp) ----
        float2 bvv[8];
        #pragma unroll
        for (int an = 0; an < 8; ++an)
            bvv[an] = *(const float2*)&bv[v0 + wn * 64 + an * 8 + l4 * 2];

        #pragma unroll
        for (int am = 0; am < 2; ++am) {
            long row0 = r0 + wm * 32 + am * 16 + q;
            long row1 = row0 + 8;
            float mx0 = -1e30f, mx1 = -1e30f;
            #pragma unroll
            for (int an = 0; an < 8; ++an) {
                acc[am][an][0] += bvv[an].x;  acc[am][an][1] += bvv[an].y;
                acc[am][an][2] += bvv[an].x;  acc[am][an][3] += bvv[an].y;
                long coff = v0 + wn * 64 + an * 8 + l4 * 2;
                *(float2*)&out[(row0 << 13) + coff] = make_float2(acc[am][an][0], acc[am][an][1]);
                *(float2*)&out[(row1 << 13) + coff] = make_float2(acc[am][an][2], acc[am][an][3]);
                mx0 = fmaxf(mx0, fmaxf(acc[am][an][0], acc[am][an][1]));
                mx1 = fmaxf(mx1, fmaxf(acc[am][an][2], acc[am][an][3]));
            }
            mx0 = fmaxf(mx0, __shfl_xor_sync(0xffffffffu, mx0, 1));
            mx0 = fmaxf(mx0, __shfl_xor_sync(0xffffffffu, mx0, 2));
            mx1 = fmaxf(mx1, __shfl_xor_sync(0xffffffffu, mx1, 1));
            mx1 = fmaxf(mx1, __shfl_xor_sync(0xffffffffu, mx1, 2));
            float s0 = 0.f, s1 = 0.f;
            #pragma unroll
            for (int an = 0; an < 8; ++an) {
                s0 += __expf(acc[am][an][0] - mx0) + __expf(acc[am][an][1] - mx0);
                s1 += __expf(acc[am][an][2] - mx1) + __expf(acc[am][an][3] - mx1);
            }
            s0 += __shfl_xor_sync(0xffffffffu, s0, 1);
            s0 += __shfl_xor_sync(0xffffffffu, s0, 2);
            s1 += __shfl_xor_sync(0xffffffffu, s1, 1);
            s1 += __shfl_xor_sync(0xffffffffu, s1, 2);
            if (l4 == 0) {
                int rl0 = wm * 32 + am * 16 + q;
                pmax[wn][rl0] = mx0;      psum[wn][rl0] = s0;
                pmax[wn][rl0 + 8] = mx1;  psum[wn][rl0 + 8] = s1;
            }
        }
        __syncthreads();
        if (tid < 128) {
            float m0 = pmax[0][tid], m1 = pmax[1][tid];
            float mo = rmax[tid];
            float mn = fmaxf(mo, fmaxf(m0, m1));
            rsum[tid] = rsum[tid] * __expf(mo - mn)
                      + psum[0][tid] * __expf(m0 - mn)
                      + psum[1][tid] * __expf(m1 - mn);
            rmax[tid] = mn;
        }
        // next chunk's first kb __syncthreads() guards pmax/psum reuse
    }
    __syncthreads();
    if (tid < 128) g_lse[r0 + tid] = rmax[tid] + logf(rsum[tid]);
}

// ---------------------------------------------------------------
// K4: out[row, v] -= lse[row]   (float4 streaming)
// ---------------------------------------------------------------
__global__ void k_sub(float* __restrict__ out) {
    long idx = (long)blockIdx.x * 256 + threadIdx.x;   // float4 index
    float l = __ldg(&g_lse[idx >> 11]);                // 2048 float4 per row
    float4* p = (float4*)out + idx;
    float4 x = *p;
    x.x -= l; x.y -= l; x.z -= l; x.w -= l;
    *p = x;
}

// ---------------------------------------------------------------
extern "C" void kernel_launch(void* const* d_in, const int* in_sizes, int n_in,
                              void* d_out, int out_size) {
    const float* v  = (const float*)d_in[0];
    const float* t  = (const float*)d_in[1];
    const float* W1 = (const float*)d_in[2];
    const float* b1 = (const float*)d_in[3];
    const float* W2 = (const float*)d_in[4];
    const float* b2 = (const float*)d_in[5];
    const float* Wv = (const float*)d_in[6];
    const float* bv = (const float*)d_in[7];
    float* out = (float*)d_out;

    k_encdec<<<640, 256>>>(v, t, W1, b1, W2, b2);
    k_cvt<<<4096, 256>>>(Wv);
    cudaFuncSetAttribute(k_gemm, cudaFuncAttributeMaxDynamicSharedMemorySize, SMEM_DYN);
    k_gemm<<<256, 256, SMEM_DYN>>>(bv, out);
    k_sub<<<262144, 256>>>(out);
}

// round 2
// speedup vs baseline: 1.0006x; 1.0006x over previous
#include <cuda_runtime.h>
#include <cuda_bf16.h>
#include <math.h>
#include <stdint.h>

// Problem constants
#define D_ 512
#define V_ 8192
#define R_ 32768   // B*T*U = 2*256*64

// -------- scratch (static device allocations only) --------
__device__ float g_enc[512 * 512];                 // (B*T, D)
__device__ float g_dec[128 * 512];                 // (B*U, D)
__device__ __nv_bfloat16 g_wvt[8192 * 512];        // Wv transposed [v][d], bf16
__device__ float g_lse[32768];                     // per-row logsumexp

// ---------------------------------------------------------------
// K1: enc = v@W1+b1 (512 rows), dec = t@W2+b2 (128 rows)
// one CTA per row, 256 threads, 2 output cols per thread
// ---------------------------------------------------------------
__global__ void k_encdec(const float* __restrict__ v, const float* __restrict__ t,
                         const float* __restrict__ W1, const float* __restrict__ b1,
                         const float* __restrict__ W2, const float* __restrict__ b2) {
    __shared__ float xrow[512];
    int bid = blockIdx.x, tid = threadIdx.x;
    const float *in, *W, *bias;
    float* out;
    if (bid < 512) { in = v + (size_t)bid * D_; W = W1; bias = b1; out = g_enc + (size_t)bid * D_; }
    else { int r = bid - 512; in = t + (size_t)r * D_; W = W2; bias = b2; out = g_dec + (size_t)r * D_; }
    xrow[tid] = in[tid];
    xrow[tid + 256] = in[tid + 256];
    __syncthreads();
    int e = tid * 2;
    float a0 = bias[e], a1 = bias[e + 1];
    #pragma unroll 4
    for (int d = 0; d < D_; ++d) {
        float x = xrow[d];
        float2 w = *(const float2*)&W[d * D_ + e];
        a0 = fmaf(x, w.x, a0);
        a1 = fmaf(x, w.y, a1);
    }
    out[e] = a0;
    out[e + 1] = a1;
}

// ---------------------------------------------------------------
// K1b: convert Wv (fp32 [d][v]) -> g_wvt (bf16 [v][d])
// ---------------------------------------------------------------
__global__ void k_cvt(const float* __restrict__ Wv) {
    int idx = blockIdx.x * 256 + threadIdx.x;   // 0 .. 1048575 (f4 groups)
    int d = idx >> 11;                          // 2048 float4 per d-row
    int v4 = idx & 2047;
    float4 w = ((const float4*)Wv)[(size_t)d * 2048 + v4];
    int vb = v4 * 4;
    g_wvt[(size_t)(vb + 0) * 512 + d] = __float2bfloat16(w.x);
    g_wvt[(size_t)(vb + 1) * 512 + d] = __float2bfloat16(w.y);
    g_wvt[(size_t)(vb + 2) * 512 + d] = __float2bfloat16(w.z);
    g_wvt[(size_t)(vb + 3) * 512 + d] = __float2bfloat16(w.w);
}

// ---------------------------------------------------------------
// K2: main GEMM + online logsumexp.
// CTA: 128 rows x full V (loops 64 chunks of N=128). 256 threads (8 warps,
// warp grid 4(M) x 2(N)). mma.sync.m16n8k16 bf16 -> fp32.
// sA: h tile [128][520] bf16 (pad -> bank step 4/row, conflict-free frags)
// sB: Wv^T chunk [128 n][136 k] bf16 (pad -> conflict-free frags)
// ---------------------------------------------------------------
__device__ __forceinline__ void mma16816(float* c, const uint32_t* a, const uint32_t* b) {
    asm("mma.sync.aligned.m16n8k16.row.col.f32.bf16.bf16.f32 "
        "{%0,%1,%2,%3}, {%4,%5,%6,%7}, {%8,%9}, {%0,%1,%2,%3};\n"
        : "+f"(c[0]), "+f"(c[1]), "+f"(c[2]), "+f"(c[3])
        : "r"(a[0]), "r"(a[1]), "r"(a[2]), "r"(a[3]), "r"(b[0]), "r"(b[1]));
}

#define SA_STRIDE 520        // bf16 units per A row (260 u32)
#define SB_STRIDE 136        // bf16 units per B row (68 u32)
#define SMEM_A_BYTES (128 * SA_STRIDE * 2)           // 133120
#define SMEM_B_BYTES (128 * SB_STRIDE * 2)           // 34816
#define SMEM_DYN (SMEM_A_BYTES + SMEM_B_BYTES)       // 167936

__global__ void __launch_bounds__(256, 1)
k_gemm(const float* __restrict__ bv, float* __restrict__ out) {
    extern __shared__ char smem[];
    __nv_bfloat16* sA = (__nv_bfloat16*)smem;
    uint32_t* sAu = (uint32_t*)smem;
    uint32_t* sBu = (uint32_t*)(smem + SMEM_A_BYTES);

    __shared__ float pmax[2][128], psum[2][128];
    __shared__ float rmax[128], rsum[128];

    int tid = threadIdx.x;
    int lane = tid & 31, warp = tid >> 5;
    int wm = warp & 3, wn = warp >> 2;     // warp grid 4 x 2
    int q = lane >> 2, l4 = lane & 3;
    int r0 = blockIdx.x * 128;

    // ---- build A tile: h = relu(enc[bt] + dec[bu]) -> bf16 ----
    for (int j = 0; j < 256; ++j) {
        int idx = j * 256 + tid;
        int rl = idx >> 9, d = idx & 511;
        int r = r0 + rl;
        int er = r >> 6;                          // b*T + t
        int dr = ((r >> 14) << 6) | (r & 63);     // b*U + u
        float hv = g_enc[(size_t)er * 512 + d] + g_dec[(size_t)dr * 512 + d];
        hv = hv > 0.f ? hv : 0.f;
        sA[rl * SA_STRIDE + d] = __float2bfloat16(hv);
    }
    if (tid < 128) { rmax[tid] = -1e30f; rsum[tid] = 0.f; }

    const uint32_t* wvu = (const uint32_t*)g_wvt;   // 256 u32 per v-row

    for (int vc = 0; vc < 64; ++vc) {
        int v0 = vc * 128;
        float acc[2][8][4];
        #pragma unroll
        for (int am = 0; am < 2; ++am)
            #pragma unroll
            for (int an = 0; an < 8; ++an)
                #pragma unroll
                for (int jj = 0; jj < 4; ++jj) acc[am][an][jj] = 0.f;

        for (int kb = 0; kb < 4; ++kb) {
            __syncthreads();   // sB (and on first iter: sA fill / pmax) safe to overwrite
            // stage sB: 128 n-rows x 64 u32 of k
            #pragma unroll
            for (int i = 0; i < 32; ++i) {
                int qq = i * 256 + tid;
                int n = qq >> 6, kk = qq & 63;
                sBu[n * 68 + kk] = wvu[(size_t)(v0 + n) * 256 + kb * 64 + kk];
            }
            __syncthreads();

            #pragma unroll
            for (int ks = 0; ks < 8; ++ks) {
                int kc = kb * 64 + ks * 8 + l4;    // u32 column in sA
                uint32_t afr[2][4];
                #pragma unroll
                for (int am = 0; am < 2; ++am) {
                    int rowb = wm * 32 + am * 16 + q;
                    const uint32_t* pa = &sAu[rowb * 260 + kc];
                    afr[am][0] = pa[0];
                    afr[am][1] = pa[8 * 260];
                    afr[am][2] = pa[4];
                    afr[am][3] = pa[8 * 260 + 4];
                }
                uint32_t bfr[8][2];
                #pragma unroll
                for (int an = 0; an < 8; ++an) {
                    const uint32_t* pb = &sBu[(wn * 64 + an * 8 + q) * 68 + ks * 8 + l4];
                    bfr[an][0] = pb[0];
                    bfr[an][1] = pb[4];
                }
                #pragma unroll
                for (int am = 0; am < 2; ++am)
                    #pragma unroll
                    for (int an = 0; an < 8; ++an)
                        mma16816(acc[am][an], afr[am], bfr[an]);
            }
        }

        // ---- epilogue: add bias, store logits, online (max, sumexp) ----
        float2 bvv[8];
        #pragma unroll
        for (int an = 0; an < 8; ++an)
            bvv[an] = *(const float2*)&bv[v0 + wn * 64 + an * 8 + l4 * 2];

        #pragma unroll
        for (int am = 0; am < 2; ++am) {
            long row0 = r0 + wm * 32 + am * 16 + q;
            long row1 = row0 + 8;
            float mx0 = -1e30f, mx1 = -1e30f;
            #pragma unroll
            for (int an = 0; an < 8; ++an) {
                acc[am][an][0] += bvv[an].x;  acc[am][an][1] += bvv[an].y;
                acc[am][an][2] += bvv[an].x;  acc[am][an][3] += bvv[an].y;
                long coff = v0 + wn * 64 + an * 8 + l4 * 2;
                *(float2*)&out[(row0 << 13) + coff] = make_float2(acc[am][an][0], acc[am][an][1]);
                *(float2*)&out[(row1 << 13) + coff] = make_float2(acc[am][an][2], acc[am][an][3]);
                mx0 = fmaxf(mx0, fmaxf(acc[am][an][0], acc[am][an][1]));
                mx1 = fmaxf(mx1, fmaxf(acc[am][an][2], acc[am][an][3]));
            }
            mx0 = fmaxf(mx0, __shfl_xor_sync(0xffffffffu, mx0, 1));
            mx0 = fmaxf(mx0, __shfl_xor_sync(0xffffffffu, mx0, 2));
            mx1 = fmaxf(mx1, __shfl_xor_sync(0xffffffffu, mx1, 1));
            mx1 = fmaxf(mx1, __shfl_xor_sync(0xffffffffu, mx1, 2));
            float s0 = 0.f, s1 = 0.f;
            #pragma unroll
            for (int an = 0; an < 8; ++an) {
                s0 += __expf(acc[am][an][0] - mx0) + __expf(acc[am][an][1] - mx0);
                s1 += __expf(acc[am][an][2] - mx1) + __expf(acc[am][an][3] - mx1);
            }
            s0 += __shfl_xor_sync(0xffffffffu, s0, 1);
            s0 += __shfl_xor_sync(0xffffffffu, s0, 2);
            s1 += __shfl_xor_sync(0xffffffffu, s1, 1);
            s1 += __shfl_xor_sync(0xffffffffu, s1, 2);
            if (l4 == 0) {
                int rl0 = wm * 32 + am * 16 + q;
                pmax[wn][rl0] = mx0;      psum[wn][rl0] = s0;
                pmax[wn][rl0 + 8] = mx1;  psum[wn][rl0 + 8] = s1;
            }
        }
        __syncthreads();
        if (tid < 128) {
            float m0 = pmax[0][tid], m1 = pmax[1][tid];
            float mo = rmax[tid];
            float mn = fmaxf(mo, fmaxf(m0, m1));
            rsum[tid] = rsum[tid] * __expf(mo - mn)
                      + psum[0][tid] * __expf(m0 - mn)
                      + psum[1][tid] * __expf(m1 - mn);
            rmax[tid] = mn;
        }
        // next chunk's first kb __syncthreads() guards pmax/psum reuse
    }
    __syncthreads();
    if (tid < 128) g_lse[r0 + tid] = rmax[tid] + logf(rsum[tid]);
}

// ---------------------------------------------------------------
// K4: out[row, v] -= lse[row]   (float4 streaming)
// ---------------------------------------------------------------
__global__ void k_sub(float* __restrict__ out) {
    long idx = (long)blockIdx.x * 256 + threadIdx.x;   // float4 index
    float l = __ldg(&g_lse[idx >> 11]);                // 2048 float4 per row
    float4* p = (float4*)out + idx;
    float4 x = *p;
    x.x -= l; x.y -= l; x.z -= l; x.w -= l;
    *p = x;
}

// ---------------------------------------------------------------
extern "C" void kernel_launch(void* const* d_in, const int* in_sizes, int n_in,
                              void* d_out, int out_size) {
    const float* v  = (const float*)d_in[0];
    const float* t  = (const float*)d_in[1];
    const float* W1 = (const float*)d_in[2];
    const float* b1 = (const float*)d_in[3];
    const float* W2 = (const float*)d_in[4];
    const float* b2 = (const float*)d_in[5];
    const float* Wv = (const float*)d_in[6];
    const float* bv = (const float*)d_in[7];
    float* out = (float*)d_out;

    k_encdec<<<640, 256>>>(v, t, W1, b1, W2, b2);
    k_cvt<<<4096, 256>>>(Wv);
    cudaFuncSetAttribute(k_gemm, cudaFuncAttributeMaxDynamicSharedMemorySize, SMEM_DYN);
    k_gemm<<<256, 256, SMEM_DYN>>>(bv, out);
    k_sub<<<262144, 256>>>(out);
}

// round 4
// speedup vs baseline: 1.1418x; 1.1411x over previous
#include <cuda_runtime.h>
#include <cuda_bf16.h>
#include <math.h>
#include <stdint.h>

#define VSZ 8192

__device__ __align__(16) float g_enc[512 * 512];
__device__ __align__(16) float g_dec[128 * 512];
__device__ __align__(16) __nv_bfloat16 g_wvt[8192 * 512];   // [v][d] bf16

// ---------------- helpers ----------------
__device__ __forceinline__ uint32_t smem_u32(const void* p) {
    uint32_t a;
    asm("{ .reg .u64 t; cvta.to.shared.u64 t, %1; cvt.u32.u64 %0, t; }" : "=r"(a) : "l"(p));
    return a;
}
__device__ __forceinline__ void cpa16(uint32_t dst, const void* src) {
    asm volatile("cp.async.cg.shared.global [%0], [%1], 16;" :: "r"(dst), "l"(src));
}
#define CPA_COMMIT() asm volatile("cp.async.commit_group;" ::: "memory")
#define CPA_WAIT1()  asm volatile("cp.async.wait_group 1;" ::: "memory")
#define CPA_WAIT0()  asm volatile("cp.async.wait_group 0;" ::: "memory")

__device__ __forceinline__ void ldsm4(uint32_t* r, uint32_t a) {
    asm volatile("ldmatrix.sync.aligned.m8n8.x4.shared.b16 {%0,%1,%2,%3}, [%4];"
        : "=r"(r[0]), "=r"(r[1]), "=r"(r[2]), "=r"(r[3]) : "r"(a));
}
__device__ __forceinline__ void mma16816(float* c, const uint32_t* a, const uint32_t* b) {
    asm("mma.sync.aligned.m16n8k16.row.col.f32.bf16.bf16.f32 "
        "{%0,%1,%2,%3}, {%4,%5,%6,%7}, {%8,%9}, {%0,%1,%2,%3};\n"
        : "+f"(c[0]), "+f"(c[1]), "+f"(c[2]), "+f"(c[3])
        : "r"(a[0]), "r"(a[1]), "r"(a[2]), "r"(a[3]), "r"(b[0]), "r"(b[1]));
}

// ---------------- prep kernels ----------------
__global__ void k_encdec(const float* __restrict__ v, const float* __restrict__ t,
                         const float* __restrict__ W1, const float* __restrict__ b1,
                         const float* __restrict__ W2, const float* __restrict__ b2) {
    __shared__ float xr[512];
    int bid = blockIdx.x, tid = threadIdx.x;
    const float *in, *W, *bs; float* out;
    if (bid < 512) { in = v + (size_t)bid * 512; W = W1; bs = b1; out = g_enc + (size_t)bid * 512; }
    else { int r = bid - 512; in = t + (size_t)r * 512; W = W2; bs = b2; out = g_dec + (size_t)r * 512; }
    xr[tid] = in[tid]; xr[tid + 256] = in[tid + 256];
    __syncthreads();
    int e = tid * 2;
    float a0 = bs[e], a1 = bs[e + 1];
    #pragma unroll 4
    for (int d = 0; d < 512; ++d) {
        float x = xr[d];
        float2 w = *(const float2*)&W[d * 512 + e];
        a0 = fmaf(x, w.x, a0); a1 = fmaf(x, w.y, a1);
    }
    out[e] = a0; out[e + 1] = a1;
}

__global__ void k_cvt(const float* __restrict__ Wv) {
    __shared__ float tile[32][33];
    int bvi = blockIdx.x & 255, bd = blockIdx.x >> 8;
    int v0 = bvi * 32, d0 = bd * 32;
    int c = threadIdx.x & 31, r8 = threadIdx.x >> 5;
    #pragma unroll
    for (int i = 0; i < 4; ++i) {
        int d = i * 8 + r8;
        tile[d][c] = Wv[(size_t)(d0 + d) * VSZ + v0 + c];
    }
    __syncthreads();
    #pragma unroll
    for (int i = 0; i < 4; ++i) {
        int vv = i * 8 + r8;
        g_wvt[(size_t)(v0 + vv) * 512 + d0 + c] = __float2bfloat16(tile[c][vv]);
    }
}

// ---------------- main GEMM + fused log-softmax ----------------
// CTA: 128 rows x full V. 8 warps, warp grid 2(M) x 4(N), warp tile 64x64.
// Chunk N=256 (32 chunks). B staged in 64-k slabs, cp.async double buffered.
// A: 128 x 512 bf16, stride 520 (ldmatrix conflict-free).
// B slab: 256 n x 64 k bf16, stride 72.
#define SA_STRB 1040                 // A row stride bytes (520 bf16)
#define SB_STRB 144                  // B row stride bytes (72 bf16)
#define A_BYTES (128 * SA_STRB)      // 133120
#define B_BYTES (256 * SB_STRB)      // 36864
#define DYN_SMEM (A_BYTES + 2 * B_BYTES)   // 206848

__global__ void __launch_bounds__(256, 1)
k_gemm2(const float* __restrict__ bv, float* __restrict__ out) {
    extern __shared__ char sm[];
    __shared__ float pmax[4][128], psum[4][128];
    __shared__ float rmax[128], rsum[128], slse[128];

    const uint32_t sA = smem_u32(sm);
    const uint32_t sB0 = sA + A_BYTES;
    int tid = threadIdx.x, lane = tid & 31, w = tid >> 5;
    int wm = w >> 2, wn = w & 3;           // 2 x 4 warp grid
    int q = lane >> 2, l4 = lane & 3;
    int r0 = blockIdx.x * 128;

    // ---- build A tile (relu(enc+dec) -> bf16) ----
    #pragma unroll 1
    for (int i = 0; i < 32; ++i) {
        int idx = i * 256 + tid;
        int r = idx >> 6, g = idx & 63;
        int grow = r0 + r;
        int er = grow >> 6;
        int dr = ((grow >> 14) << 6) | (grow & 63);
        const float* ep = g_enc + (size_t)er * 512 + g * 8;
        const float* dp = g_dec + (size_t)dr * 512 + g * 8;
        float4 e0 = *(const float4*)ep, e1 = *(const float4*)(ep + 4);
        float4 d0 = *(const float4*)dp, d1 = *(const float4*)(dp + 4);
        __nv_bfloat162 p0 = __floats2bfloat162_rn(fmaxf(e0.x + d0.x, 0.f), fmaxf(e0.y + d0.y, 0.f));
        __nv_bfloat162 p1 = __floats2bfloat162_rn(fmaxf(e0.z + d0.z, 0.f), fmaxf(e0.w + d0.w, 0.f));
        __nv_bfloat162 p2 = __floats2bfloat162_rn(fmaxf(e1.x + d1.x, 0.f), fmaxf(e1.y + d1.y, 0.f));
        __nv_bfloat162 p3 = __floats2bfloat162_rn(fmaxf(e1.z + d1.z, 0.f), fmaxf(e1.w + d1.w, 0.f));
        uint4 u;
        u.x = *(unsigned*)&p0; u.y = *(unsigned*)&p1; u.z = *(unsigned*)&p2; u.w = *(unsigned*)&p3;
        *(uint4*)(sm + r * SA_STRB + g * 16) = u;
    }
    if (tid < 128) { rmax[tid] = -1e30f; rsum[tid] = 0.f; }

    // per-lane ldmatrix base addresses
    const uint32_t aBase = sA + (wm * 64 + (lane & 15)) * SA_STRB + (lane >> 4) * 16;
    const int bN = (lane & 7) + ((lane >> 4) << 3);
    const uint32_t bKh = ((lane >> 3) & 1) * 16;
    const uint32_t bBase = sB0 + (wn * 64 + bN) * SB_STRB + bKh;

    float acc[4][8][4];

    // stage 0 (vc=0, kb=0)
    {
        uint32_t dst = sB0;
        #pragma unroll
        for (int i = 0; i < 8; ++i) {
            int flat = i * 256 + tid;
            int n = flat >> 3, c = flat & 7;
            cpa16(dst + n * SB_STRB + c * 16,
                  (const char*)g_wvt + (size_t)n * 1024 + c * 16);
        }
        CPA_COMMIT();
    }

    #pragma unroll 1
    for (int s = 0; s < 256; ++s) {
        int vc = s >> 3, kb = s & 7, buf = s & 1;
        __syncthreads();                       // everyone done with slab s-1
        if (s + 1 < 256) {
            int vn = (s + 1) >> 3, kn = (s + 1) & 7;
            uint32_t dst = sB0 + ((s + 1) & 1) * B_BYTES;
            const char* src = (const char*)g_wvt + (size_t)vn * 256 * 1024 + kn * 128;
            #pragma unroll
            for (int i = 0; i < 8; ++i) {
                int flat = i * 256 + tid;
                int n = flat >> 3, c = flat & 7;
                cpa16(dst + n * SB_STRB + c * 16, src + (size_t)n * 1024 + c * 16);
            }
            CPA_COMMIT();
            CPA_WAIT1();                       // slab s complete
        } else {
            CPA_WAIT0();
        }
        __syncthreads();

        if (kb == 0) {
            #pragma unroll
            for (int am = 0; am < 4; ++am)
                #pragma unroll
                for (int an = 0; an < 8; ++an)
                    #pragma unroll
                    for (int j = 0; j < 4; ++j) acc[am][an][j] = 0.f;
        }

        uint32_t bB = bBase + buf * B_BYTES;
        uint32_t aK = aBase + kb * 128;
        #pragma unroll
        for (int ks = 0; ks < 4; ++ks) {
            uint32_t afr[4][4], bfr[4][4];
            #pragma unroll
            for (int am = 0; am < 4; ++am) ldsm4(afr[am], aK + am * 16 * SA_STRB + ks * 32);
            #pragma unroll
            for (int t = 0; t < 4; ++t) ldsm4(bfr[t], bB + t * 16 * SB_STRB + ks * 32);
            #pragma unroll
            for (int am = 0; am < 4; ++am)
                #pragma unroll
                for (int t = 0; t < 4; ++t) {
                    mma16816(acc[am][2 * t],     afr[am], &bfr[t][0]);
                    mma16816(acc[am][2 * t + 1], afr[am], &bfr[t][2]);
                }
        }

        if (kb == 7) {
            // ---- epilogue for chunk vc: bias, store logits, lse partials ----
            int v0 = vc * 256;
            float2 bvv[8];
            #pragma unroll
            for (int an = 0; an < 8; ++an)
                bvv[an] = *(const float2*)&bv[v0 + wn * 64 + an * 8 + l4 * 2];
            #pragma unroll
            for (int am = 0; am < 4; ++am) {
                int rowl = wm * 64 + am * 16 + q;
                size_t gr0 = (size_t)(r0 + rowl) << 13;
                size_t gr1 = gr0 + (8u << 13);
                float mx0 = -1e30f, mx1 = -1e30f;
                #pragma unroll
                for (int an = 0; an < 8; ++an) {
                    float* a4 = acc[am][an];
                    a4[0] += bvv[an].x; a4[1] += bvv[an].y;
                    a4[2] += bvv[an].x; a4[3] += bvv[an].y;
                    size_t coff = v0 + wn * 64 + an * 8 + l4 * 2;
                    *(float2*)&out[gr0 + coff] = make_float2(a4[0], a4[1]);
                    *(float2*)&out[gr1 + coff] = make_float2(a4[2], a4[3]);
                    mx0 = fmaxf(mx0, fmaxf(a4[0], a4[1]));
                    mx1 = fmaxf(mx1, fmaxf(a4[2], a4[3]));
                }
                mx0 = fmaxf(mx0, __shfl_xor_sync(~0u, mx0, 1));
                mx0 = fmaxf(mx0, __shfl_xor_sync(~0u, mx0, 2));
                mx1 = fmaxf(mx1, __shfl_xor_sync(~0u, mx1, 1));
                mx1 = fmaxf(mx1, __shfl_xor_sync(~0u, mx1, 2));
                float s0 = 0.f, s1 = 0.f;
                #pragma unroll
                for (int an = 0; an < 8; ++an) {
                    float* a4 = acc[am][an];
                    s0 += __expf(a4[0] - mx0) + __expf(a4[1] - mx0);
                    s1 += __expf(a4[2] - mx1) + __expf(a4[3] - mx1);
                }
                s0 += __shfl_xor_sync(~0u, s0, 1);
                s0 += __shfl_xor_sync(~0u, s0, 2);
                s1 += __shfl_xor_sync(~0u, s1, 1);
                s1 += __shfl_xor_sync(~0u, s1, 2);
                if (l4 == 0) {
                    pmax[wn][rowl] = mx0;     psum[wn][rowl] = s0;
                    pmax[wn][rowl + 8] = mx1; psum[wn][rowl + 8] = s1;
                }
            }
            __syncthreads();
            if (tid < 128) {
                float m0 = pmax[0][tid], m1 = pmax[1][tid];
                float m2 = pmax[2][tid], m3 = pmax[3][tid];
                float mo = rmax[tid];
                float mn = fmaxf(fmaxf(fmaxf(m0, m1), fmaxf(m2, m3)), mo);
                rsum[tid] = rsum[tid] * __expf(mo - mn)
                          + psum[0][tid] * __expf(m0 - mn)
                          + psum[1][tid] * __expf(m1 - mn)
                          + psum[2][tid] * __expf(m2 - mn)
                          + psum[3][tid] * __expf(m3 - mn);
                rmax[tid] = mn;
            }
        }
    }

    // ---- fused fixup: out -= lse over this CTA's 128 rows ----
    __syncthreads();
    if (tid < 128) slse[tid] = rmax[tid] + logf(rsum[tid]);
    __syncthreads();
    float4* ob = (float4*)(out + ((size_t)r0 << 13));
    #pragma unroll 4
    for (int it = 0; it < 1024; ++it) {
        int idx = it * 256 + tid;
        float l = slse[idx >> 11];
        float4 x = ob[idx];
        x.x -= l; x.y -= l; x.z -= l; x.w -= l;
        ob[idx] = x;
    }
}

// ---------------------------------------------------------------
extern "C" void kernel_launch(void* const* d_in, const int* in_sizes, int n_in,
                              void* d_out, int out_size) {
    (void)in_sizes; (void)n_in; (void)out_size;
    const float* v  = (const float*)d_in[0];
    const float* t  = (const float*)d_in[1];
    const float* W1 = (const float*)d_in[2];
    const float* b1 = (const float*)d_in[3];
    const float* W2 = (const float*)d_in[4];
    const float* b2 = (const float*)d_in[5];
    const float* Wv = (const float*)d_in[6];
    const float* bvp = (const float*)d_in[7];
    float* out = (float*)d_out;

    k_encdec<<<640, 256>>>(v, t, W1, b1, W2, b2);
    k_cvt<<<4096, 256>>>(Wv);
    cudaFuncSetAttribute(k_gemm2, cudaFuncAttributeMaxDynamicSharedMemorySize, DYN_SMEM);
    k_gemm2<<<256, 256, DYN_SMEM>>>(bvp, out);
}